// round 6
// baseline (speedup 1.0000x reference)
#include <cuda_runtime.h>
#include <cuda_bf16.h>
#include <cstdint>

#define BATCH 16
#define CC 512
#define HW 1024
#define G 32
#define CG 16
#define EPS 1e-5f

typedef __nv_bfloat16 bf16;

// ---------------------------------------------------------------------------
// Scratch (device globals)
// ---------------------------------------------------------------------------
__device__ float g_stats[BATCH * G * 2];
__device__ __align__(16) bf16 g_ht_hi[BATCH * HW * CC], g_ht_lo[BATCH * HW * CC];
__device__ __align__(16) bf16 g_qt_hi[BATCH * HW * CC], g_qt_lo[BATCH * HW * CC];
__device__ __align__(16) bf16 g_kt_hi[BATCH * HW * CC], g_kt_lo[BATCH * HW * CC];
__device__ __align__(16) bf16 g_v_hi[BATCH * CC * HW],  g_v_lo[BATCH * CC * HW];
__device__ __align__(16) float g_s[(size_t)BATCH * HW * HW];
__device__ __align__(16) bf16 g_p_hi[(size_t)BATCH * HW * HW];
__device__ __align__(16) bf16 g_p_lo[(size_t)BATCH * HW * HW];
__device__ __align__(16) bf16 g_ot_hi[BATCH * HW * CC], g_ot_lo[BATCH * HW * CC];
__device__ __align__(16) bf16 g_w_hi[4 * CC * CC], g_w_lo[4 * CC * CC];

// ---------------------------------------------------------------------------
// PTX helpers
// ---------------------------------------------------------------------------
__device__ __forceinline__ uint32_t smem_u32(const void* p) {
    uint32_t a;
    asm("{ .reg .u64 t; cvta.to.shared.u64 t, %1; cvt.u32.u64 %0, t; }"
        : "=r"(a) : "l"(p));
    return a;
}
__device__ __forceinline__ void cpa16(uint32_t dst, const void* src) {
    asm volatile("cp.async.ca.shared.global [%0], [%1], 16;"
                 :: "r"(dst), "l"(src));
}
#define CP_COMMIT() asm volatile("cp.async.commit_group;" ::: "memory")
#define CP_WAIT1() asm volatile("cp.async.wait_group 1;" ::: "memory")

__device__ __forceinline__ void ldsm_x4(uint32_t* r, uint32_t addr) {
    asm volatile(
        "ldmatrix.sync.aligned.m8n8.x4.shared.b16 {%0,%1,%2,%3}, [%4];"
        : "=r"(r[0]), "=r"(r[1]), "=r"(r[2]), "=r"(r[3]) : "r"(addr));
}
__device__ __forceinline__ void mma16816(float* c, const uint32_t* a,
                                         const uint32_t* b) {
    asm volatile(
        "mma.sync.aligned.m16n8k16.row.col.f32.bf16.bf16.f32 "
        "{%0,%1,%2,%3}, {%4,%5,%6,%7}, {%8,%9}, {%0,%1,%2,%3};"
        : "+f"(c[0]), "+f"(c[1]), "+f"(c[2]), "+f"(c[3])
        : "r"(a[0]), "r"(a[1]), "r"(a[2]), "r"(a[3]), "r"(b[0]), "r"(b[1]));
}

// Swizzled 64B-row layout: conflict-free for ldmatrix + cp.async
// byte offset within a matrix for (row, logical k-byte kb, kb%16==0):
#define SWZ(row, kb) \
    ((uint32_t)(row) * 64u + (((((uint32_t)(kb)) >> 4) ^ (((uint32_t)(row) >> 1) & 3u)) << 4))

#define MATB 8192u           // 128 rows * 64 B
#define STAGEB 32768u        // 4 matrices (Ah, Al, Bh, Bl)
#define NSTAGE 3
#define SMEM_TOTAL (NSTAGE * STAGEB)

// ---------------------------------------------------------------------------
// Split-bf16 MMA GEMM: D[m][n] = sum_k A[m][k]*B[n][k]  (both K-contiguous)
// 128x128 tile, BK=32, 256 thr (8 warps, 32x64 warp tiles),
// 3-stage cp.async pipeline, one barrier per K-step, swizzled smem.
// MODE 0: +bias[n], bf16 hi/lo out     (Q/K proj)
// MODE 1: +bias[m], bf16 hi/lo out     (V proj)
// MODE 2: *scale,   f32 out            (scores)
// MODE 3: plain,    bf16 hi/lo out     (attn @ V)
// MODE 4: +bias[m]+resid, f32 out      (final proj)
// ---------------------------------------------------------------------------
template <int MODE>
__global__ void __launch_bounds__(256, 2)
gemm_mma(const bf16* __restrict__ Ahi, const bf16* __restrict__ Alo, size_t sA,
         const bf16* __restrict__ Bhi, const bf16* __restrict__ Blo, size_t sB,
         int K, const float* __restrict__ bias, float scale,
         const float* __restrict__ resid,
         bf16* __restrict__ Ohi, bf16* __restrict__ Olo, float* __restrict__ Of,
         int ldO, size_t sO) {
    extern __shared__ char smem[];
    const uint32_t sb = smem_u32(smem);

    const int t = threadIdx.x;
    const int w = t >> 5, lane = t & 31;
    const int g = lane >> 2, tg = lane & 3;
    const int wm = (w >> 1) * 32, wn = (w & 1) * 64;
    const int bz = blockIdx.z;
    const int n0 = blockIdx.x * 128, m0 = blockIdx.y * 128;

    const bf16* arh = Ahi + bz * sA + (size_t)m0 * K;
    const bf16* arl = Alo + bz * sA + (size_t)m0 * K;
    const bf16* brh = Bhi + bz * sB + (size_t)n0 * K;
    const bf16* brl = Blo + bz * sB + (size_t)n0 * K;

    float acc[2][8][4];
#pragma unroll
    for (int i = 0; i < 2; i++)
#pragma unroll
        for (int j = 0; j < 8; j++)
#pragma unroll
            for (int e = 0; e < 4; e++) acc[i][j][e] = 0.f;

    // cp.async loader mapping: 512 16B segs per matrix, 2 per thread
    const int row_l = t >> 2, seg = t & 3;
    const uint32_t soff0 = SWZ(row_l, seg * 16);
    const uint32_t soff1 = SWZ(row_l + 64, seg * 16);

    // ldmatrix lane address components
    const uint32_t a_row = (uint32_t)(wm + ((lane >> 3) & 1) * 8 + (lane & 7));
    const uint32_t a_kb = ((lane >> 4) & 1) * 16;
    const uint32_t b_row = (uint32_t)(wn + ((lane >> 4) & 1) * 8 + (lane & 7));
    const uint32_t b_kb = ((lane >> 3) & 1) * 16;

    const int nsteps = K >> 5;

    // issue one stage's cp.asyncs
    auto issue = [&](int s) {
        int kc = s << 5;
        uint32_t b0 = sb + (uint32_t)(s % NSTAGE) * STAGEB;
        size_t g0 = (size_t)row_l * K + kc + seg * 8;
        size_t g1 = (size_t)(row_l + 64) * K + kc + seg * 8;
        cpa16(b0 + soff0, arh + g0);            cpa16(b0 + soff1, arh + g1);
        cpa16(b0 + MATB + soff0, arl + g0);     cpa16(b0 + MATB + soff1, arl + g1);
        cpa16(b0 + 2 * MATB + soff0, brh + g0); cpa16(b0 + 2 * MATB + soff1, brh + g1);
        cpa16(b0 + 3 * MATB + soff0, brl + g0); cpa16(b0 + 3 * MATB + soff1, brl + g1);
        CP_COMMIT();
    };

    issue(0);
    issue(1);

    for (int s = 0; s < nsteps; s++) {
        CP_WAIT1();           // <=1 group pending -> stage s resident
        __syncthreads();      // all data visible; stage s-1 free to overwrite
        if (s + 2 < nsteps) issue(s + 2);

        uint32_t stg = sb + (uint32_t)(s % NSTAGE) * STAGEB;
        uint32_t pAh = stg, pAl = stg + MATB;
        uint32_t pBh = stg + 2 * MATB, pBl = stg + 3 * MATB;
#pragma unroll
        for (int kk = 0; kk < 2; kk++) {
            uint32_t kb = (uint32_t)kk * 32;
            uint32_t Ah[2][4], Al[2][4];
#pragma unroll
            for (int mf = 0; mf < 2; mf++) {
                uint32_t ad = SWZ(a_row + mf * 16, kb + a_kb);
                ldsm_x4(Ah[mf], pAh + ad);
                ldsm_x4(Al[mf], pAl + ad);
            }
#pragma unroll
            for (int p = 0; p < 4; p++) {
                uint32_t bd = SWZ(b_row + p * 16, kb + b_kb);
                uint32_t Bh[4], Bl[4];
                ldsm_x4(Bh, pBh + bd);
                ldsm_x4(Bl, pBl + bd);
#pragma unroll
                for (int mf = 0; mf < 2; mf++) {
                    mma16816(acc[mf][2 * p], Ah[mf], Bh);
                    mma16816(acc[mf][2 * p], Ah[mf], Bl);
                    mma16816(acc[mf][2 * p], Al[mf], Bh);
                    mma16816(acc[mf][2 * p + 1], Ah[mf], Bh + 2);
                    mma16816(acc[mf][2 * p + 1], Ah[mf], Bl + 2);
                    mma16816(acc[mf][2 * p + 1], Al[mf], Bh + 2);
                }
            }
        }
    }

    // ---- epilogue: direct row-major [m][n] store -------------------------
#pragma unroll
    for (int mf = 0; mf < 2; mf++) {
        int mA = m0 + wm + mf * 16 + g;
        int mB = mA + 8;
        float bmA = 0.f, bmB = 0.f;
        if (MODE == 1 || MODE == 4) { bmA = bias[mA]; bmB = bias[mB]; }
#pragma unroll
        for (int nf = 0; nf < 8; nf++) {
            int n = n0 + wn + nf * 8 + tg * 2;
            float v0 = acc[mf][nf][0], v1 = acc[mf][nf][1];
            float v2 = acc[mf][nf][2], v3 = acc[mf][nf][3];
            if (MODE == 0) {
                float bn0 = bias[n], bn1 = bias[n + 1];
                v0 += bn0; v1 += bn1; v2 += bn0; v3 += bn1;
            }
            if (MODE == 1 || MODE == 4) { v0 += bmA; v1 += bmA; v2 += bmB; v3 += bmB; }
            if (MODE == 2) { v0 *= scale; v1 *= scale; v2 *= scale; v3 *= scale; }
            size_t iA = bz * sO + (size_t)mA * ldO + n;
            size_t iB = bz * sO + (size_t)mB * ldO + n;
            if (MODE == 4) {
                v0 += resid[iA]; v1 += resid[iA + 1];
                v2 += resid[iB]; v3 += resid[iB + 1];
            }
            if (MODE == 2 || MODE == 4) {
                *(float2*)&Of[iA] = make_float2(v0, v1);
                *(float2*)&Of[iB] = make_float2(v2, v3);
            } else {
                bf16 h0 = __float2bfloat16(v0), h1 = __float2bfloat16(v1);
                bf16 h2 = __float2bfloat16(v2), h3 = __float2bfloat16(v3);
                __nv_bfloat162 hA; hA.x = h0; hA.y = h1;
                __nv_bfloat162 hB; hB.x = h2; hB.y = h3;
                *(__nv_bfloat162*)&Ohi[iA] = hA;
                *(__nv_bfloat162*)&Ohi[iB] = hB;
                __nv_bfloat162 lA, lB;
                lA.x = __float2bfloat16(v0 - __bfloat162float(h0));
                lA.y = __float2bfloat16(v1 - __bfloat162float(h1));
                lB.x = __float2bfloat16(v2 - __bfloat162float(h2));
                lB.y = __float2bfloat16(v3 - __bfloat162float(h3));
                *(__nv_bfloat162*)&Olo[iA] = lA;
                *(__nv_bfloat162*)&Olo[iB] = lB;
            }
        }
    }
}

// ---------------------------------------------------------------------------
// GroupNorm stats
// ---------------------------------------------------------------------------
__global__ void gn_stats(const float* __restrict__ x) {
    int bg = blockIdx.x;
    int bb = bg / G, g = bg % G;
    const float* xp = x + ((size_t)bb * CC + (size_t)g * CG) * HW;
    const int n = CG * HW;

    float s = 0.f, ss = 0.f;
    for (int i = threadIdx.x; i < n; i += blockDim.x) {
        float v = xp[i];
        s += v;
        ss += v * v;
    }
    __shared__ float sh0[256], sh1[256];
    sh0[threadIdx.x] = s;
    sh1[threadIdx.x] = ss;
    __syncthreads();
    for (int o = 128; o > 0; o >>= 1) {
        if (threadIdx.x < o) {
            sh0[threadIdx.x] += sh0[threadIdx.x + o];
            sh1[threadIdx.x] += sh1[threadIdx.x + o];
        }
        __syncthreads();
    }
    if (threadIdx.x == 0) {
        float mu = sh0[0] / n;
        float var = sh1[0] / n - mu * mu;
        g_stats[bg * 2] = mu;
        g_stats[bg * 2 + 1] = rsqrtf(var + EPS);
    }
}

// GroupNorm apply + transpose: x[b][c][i] -> Ht[b][i][c] bf16 hi/lo
__global__ void gn_transpose(const float* __restrict__ x,
                             const float* __restrict__ gw,
                             const float* __restrict__ gb) {
    __shared__ float tile[32][33];
    int bz = blockIdx.z;
    int i0 = blockIdx.x * 32, c0 = blockIdx.y * 32;
    int tx = threadIdx.x, ty = threadIdx.y;
    const float* xb = x + (size_t)bz * CC * HW;
#pragma unroll
    for (int r = 0; r < 4; r++) {
        int c = c0 + ty + r * 8;
        float mu = g_stats[(bz * G + (c >> 4)) * 2];
        float ri = g_stats[(bz * G + (c >> 4)) * 2 + 1];
        float v = xb[(size_t)c * HW + i0 + tx];
        tile[ty + r * 8][tx] = (v - mu) * ri * gw[c] + gb[c];
    }
    __syncthreads();
    size_t ob = (size_t)bz * HW * CC;
#pragma unroll
    for (int r = 0; r < 4; r++) {
        int i = i0 + ty + r * 8;
        float v = tile[tx][ty + r * 8];
        bf16 h = __float2bfloat16(v);
        size_t idx = ob + (size_t)i * CC + c0 + tx;
        g_ht_hi[idx] = h;
        g_ht_lo[idx] = __float2bfloat16(v - __bfloat162float(h));
    }
}

// fp32 -> bf16 hi/lo split for all 4 weight matrices in one launch
__global__ void wconv4(const float* __restrict__ w0, const float* __restrict__ w1,
                       const float* __restrict__ w2, const float* __restrict__ w3,
                       bf16* __restrict__ hi, bf16* __restrict__ lo) {
    const int NW = CC * CC;
    int i = blockIdx.x * blockDim.x + threadIdx.x;
    int which = blockIdx.y;
    const float* w = which == 0 ? w0 : which == 1 ? w1 : which == 2 ? w2 : w3;
    float v = w[i];
    bf16 h = __float2bfloat16(v);
    hi[which * NW + i] = h;
    lo[which * NW + i] = __float2bfloat16(v - __bfloat162float(h));
}

// Row softmax over 1024 columns; writes P as bf16 hi/lo
__global__ void softmax_kernel(const float* __restrict__ S,
                               bf16* __restrict__ Ph, bf16* __restrict__ Pl) {
    const float* row = S + (size_t)blockIdx.x * HW;
    int t = threadIdx.x;
    float4 v = ((const float4*)row)[t];

    __shared__ float sh[256];
    float m = fmaxf(fmaxf(v.x, v.y), fmaxf(v.z, v.w));
    sh[t] = m;
    __syncthreads();
    for (int o = 128; o > 0; o >>= 1) {
        if (t < o) sh[t] = fmaxf(sh[t], sh[t + o]);
        __syncthreads();
    }
    m = sh[0];
    __syncthreads();

    v.x = __expf(v.x - m); v.y = __expf(v.y - m);
    v.z = __expf(v.z - m); v.w = __expf(v.w - m);
    sh[t] = v.x + v.y + v.z + v.w;
    __syncthreads();
    for (int o = 128; o > 0; o >>= 1) {
        if (t < o) sh[t] += sh[t + o];
        __syncthreads();
    }
    float inv = 1.0f / sh[0];
    float p[4] = {v.x * inv, v.y * inv, v.z * inv, v.w * inv};
    size_t base = (size_t)blockIdx.x * HW + t * 4;
#pragma unroll
    for (int e = 0; e < 4; e++) {
        bf16 h = __float2bfloat16(p[e]);
        Ph[base + e] = h;
        Pl[base + e] = __float2bfloat16(p[e] - __bfloat162float(h));
    }
}

// ---------------------------------------------------------------------------
extern "C" void kernel_launch(void* const* d_in, const int* in_sizes, int n_in,
                              void* d_out, int out_size) {
    const float* x    = (const float*)d_in[0];
    const float* gn_w = (const float*)d_in[2];
    const float* gn_b = (const float*)d_in[3];
    const float* q_w  = (const float*)d_in[4];
    const float* q_b  = (const float*)d_in[5];
    const float* k_w  = (const float*)d_in[6];
    const float* k_b  = (const float*)d_in[7];
    const float* v_w  = (const float*)d_in[8];
    const float* v_b  = (const float*)d_in[9];
    const float* p_w  = (const float*)d_in[10];
    const float* p_b  = (const float*)d_in[11];
    float* out = (float*)d_out;

    bf16 *ht_hi, *ht_lo, *qt_hi, *qt_lo, *kt_hi, *kt_lo, *v_hi, *v_lo;
    bf16 *p_hi, *p_lo, *ot_hi, *ot_lo, *w_hi, *w_lo;
    float* s;
    cudaGetSymbolAddress((void**)&ht_hi, g_ht_hi);
    cudaGetSymbolAddress((void**)&ht_lo, g_ht_lo);
    cudaGetSymbolAddress((void**)&qt_hi, g_qt_hi);
    cudaGetSymbolAddress((void**)&qt_lo, g_qt_lo);
    cudaGetSymbolAddress((void**)&kt_hi, g_kt_hi);
    cudaGetSymbolAddress((void**)&kt_lo, g_kt_lo);
    cudaGetSymbolAddress((void**)&v_hi, g_v_hi);
    cudaGetSymbolAddress((void**)&v_lo, g_v_lo);
    cudaGetSymbolAddress((void**)&p_hi, g_p_hi);
    cudaGetSymbolAddress((void**)&p_lo, g_p_lo);
    cudaGetSymbolAddress((void**)&ot_hi, g_ot_hi);
    cudaGetSymbolAddress((void**)&ot_lo, g_ot_lo);
    cudaGetSymbolAddress((void**)&w_hi, g_w_hi);
    cudaGetSymbolAddress((void**)&w_lo, g_w_lo);
    cudaGetSymbolAddress((void**)&s, g_s);

    cudaFuncSetAttribute(gemm_mma<0>, cudaFuncAttributeMaxDynamicSharedMemorySize, SMEM_TOTAL);
    cudaFuncSetAttribute(gemm_mma<1>, cudaFuncAttributeMaxDynamicSharedMemorySize, SMEM_TOTAL);
    cudaFuncSetAttribute(gemm_mma<2>, cudaFuncAttributeMaxDynamicSharedMemorySize, SMEM_TOTAL);
    cudaFuncSetAttribute(gemm_mma<3>, cudaFuncAttributeMaxDynamicSharedMemorySize, SMEM_TOTAL);
    cudaFuncSetAttribute(gemm_mma<4>, cudaFuncAttributeMaxDynamicSharedMemorySize, SMEM_TOTAL);

    const size_t sHC = (size_t)HW * CC;
    const size_t sSS = (size_t)HW * HW;
    const int NW = CC * CC;
    const float scale = 0.044194173824159216f;  // 512^-0.5

    gn_stats<<<BATCH * G, 256>>>(x);
    gn_transpose<<<dim3(HW / 32, CC / 32, BATCH), dim3(32, 8)>>>(x, gn_w, gn_b);
    wconv4<<<dim3(NW / 256, 4), 256>>>(q_w, k_w, v_w, p_w, w_hi, w_lo);

    // Qt[i][c] = Ht[i]·Wq[c] + qb[c]   (bias on n)
    gemm_mma<0><<<dim3(4, 8, BATCH), 256, SMEM_TOTAL>>>(
        ht_hi, ht_lo, sHC, w_hi + 0 * NW, w_lo + 0 * NW, 0, CC,
        q_b, 0.f, nullptr, qt_hi, qt_lo, nullptr, CC, sHC);
    // Kt[i][c]
    gemm_mma<0><<<dim3(4, 8, BATCH), 256, SMEM_TOTAL>>>(
        ht_hi, ht_lo, sHC, w_hi + 1 * NW, w_lo + 1 * NW, 0, CC,
        k_b, 0.f, nullptr, kt_hi, kt_lo, nullptr, CC, sHC);
    // V[c][j] = Wv[c]·Ht[j] + vb[c]    (bias on m)
    gemm_mma<1><<<dim3(8, 4, BATCH), 256, SMEM_TOTAL>>>(
        w_hi + 2 * NW, w_lo + 2 * NW, 0, ht_hi, ht_lo, sHC, CC,
        v_b, 0.f, nullptr, v_hi, v_lo, nullptr, HW, sHC);
    // S[i][j] = scale * Qt[i]·Kt[j]
    gemm_mma<2><<<dim3(8, 8, BATCH), 256, SMEM_TOTAL>>>(
        qt_hi, qt_lo, sHC, kt_hi, kt_lo, sHC, CC,
        nullptr, scale, nullptr, nullptr, nullptr, s, HW, sSS);

    softmax_kernel<<<BATCH * HW, 256>>>(s, p_hi, p_lo);

    // Ot[i][c] = P[i]·V[c]   (K = 1024)
    gemm_mma<3><<<dim3(4, 8, BATCH), 256, SMEM_TOTAL>>>(
        p_hi, p_lo, sSS, v_hi, v_lo, sHC, HW,
        nullptr, 0.f, nullptr, ot_hi, ot_lo, nullptr, CC, sHC);
    // out[d][i] = x[d][i] + Wp[d]·Ot[i] + pb[d]
    gemm_mma<4><<<dim3(8, 4, BATCH), 256, SMEM_TOTAL>>>(
        w_hi + 3 * NW, w_lo + 3 * NW, 0, ot_hi, ot_lo, sHC, CC,
        p_b, 0.f, x, nullptr, nullptr, out, HW, sHC);
}

// round 7
// speedup vs baseline: 1.0087x; 1.0087x over previous
#include <cuda_runtime.h>
#include <cuda_bf16.h>
#include <cstdint>

#define BATCH 16
#define CC 512
#define HW 1024
#define G 32
#define CG 16
#define EPS 1e-5f

typedef __nv_bfloat16 bf16;

// ---------------------------------------------------------------------------
// Scratch (device globals)
// ---------------------------------------------------------------------------
__device__ float g_stats[BATCH * G * 2];
__device__ __align__(16) bf16 g_ht_hi[BATCH * HW * CC], g_ht_lo[BATCH * HW * CC];
__device__ __align__(16) bf16 g_qt_hi[BATCH * HW * CC], g_qt_lo[BATCH * HW * CC];
__device__ __align__(16) bf16 g_kt_hi[BATCH * HW * CC], g_kt_lo[BATCH * HW * CC];
__device__ __align__(16) bf16 g_v_hi[BATCH * CC * HW],  g_v_lo[BATCH * CC * HW];
__device__ __align__(16) float g_s[(size_t)BATCH * HW * HW];
__device__ __align__(16) bf16 g_p_hi[(size_t)BATCH * HW * HW];
__device__ __align__(16) bf16 g_p_lo[(size_t)BATCH * HW * HW];
__device__ __align__(16) bf16 g_ot_hi[BATCH * HW * CC], g_ot_lo[BATCH * HW * CC];
__device__ __align__(16) bf16 g_w_hi[4 * CC * CC], g_w_lo[4 * CC * CC];

// ---------------------------------------------------------------------------
// PTX helpers
// ---------------------------------------------------------------------------
__device__ __forceinline__ uint32_t smem_u32(const void* p) {
    uint32_t a;
    asm("{ .reg .u64 t; cvta.to.shared.u64 t, %1; cvt.u32.u64 %0, t; }"
        : "=r"(a) : "l"(p));
    return a;
}
__device__ __forceinline__ void cpa16(uint32_t dst, const void* src) {
    asm volatile("cp.async.ca.shared.global [%0], [%1], 16;"
                 :: "r"(dst), "l"(src));
}
#define CP_COMMIT() asm volatile("cp.async.commit_group;" ::: "memory")
#define CP_WAIT1() asm volatile("cp.async.wait_group 1;" ::: "memory")

__device__ __forceinline__ void ldsm_x4(uint32_t* r, uint32_t addr) {
    asm volatile(
        "ldmatrix.sync.aligned.m8n8.x4.shared.b16 {%0,%1,%2,%3}, [%4];"
        : "=r"(r[0]), "=r"(r[1]), "=r"(r[2]), "=r"(r[3]) : "r"(addr));
}
__device__ __forceinline__ void mma16816(float* c, const uint32_t* a,
                                         const uint32_t* b) {
    asm volatile(
        "mma.sync.aligned.m16n8k16.row.col.f32.bf16.bf16.f32 "
        "{%0,%1,%2,%3}, {%4,%5,%6,%7}, {%8,%9}, {%0,%1,%2,%3};"
        : "+f"(c[0]), "+f"(c[1]), "+f"(c[2]), "+f"(c[3])
        : "r"(a[0]), "r"(a[1]), "r"(a[2]), "r"(a[3]), "r"(b[0]), "r"(b[1]));
}

// Swizzled 64B-row layout: conflict-free for ldmatrix + cp.async
#define SWZ(row, kb) \
    ((uint32_t)(row) * 64u + (((((uint32_t)(kb)) >> 4) ^ (((uint32_t)(row) >> 1) & 3u)) << 4))

#define MATB 8192u           // 128 rows * 64 B
#define STAGEB 32768u        // 4 matrices (Ah, Al, Bh, Bl)
#define NSTAGE 3
#define SMEM_TOTAL (NSTAGE * STAGEB)

// ---------------------------------------------------------------------------
// Split-bf16 MMA GEMM: D[m][n] = sum_k A[m][k]*B[n][k]  (both K-contiguous)
// 128x128 tile, BK=32, 128 thr (4 warps, 64x64 warp tiles),
// 3-stage cp.async pipeline, swizzled smem, 2 CTAs/SM.
// MODE 0: +bias[n], bf16 hi/lo out     (Q/K proj)
// MODE 1: +bias[m], bf16 hi/lo out     (V proj)
// MODE 2: *scale,   f32 out            (scores)
// MODE 3: plain,    bf16 hi/lo out     (attn @ V)
// MODE 4: +bias[m]+resid, f32 out      (final proj)
// ---------------------------------------------------------------------------
template <int MODE>
__global__ void __launch_bounds__(128, 2)
gemm_mma(const bf16* __restrict__ Ahi, const bf16* __restrict__ Alo, size_t sA,
         const bf16* __restrict__ Bhi, const bf16* __restrict__ Blo, size_t sB,
         int K, const float* __restrict__ bias, float scale,
         const float* __restrict__ resid,
         bf16* __restrict__ Ohi, bf16* __restrict__ Olo, float* __restrict__ Of,
         int ldO, size_t sO) {
    extern __shared__ char smem[];
    const uint32_t sb = smem_u32(smem);

    const int t = threadIdx.x;
    const int w = t >> 5, lane = t & 31;
    const int g = lane >> 2, tg = lane & 3;
    const int wm = (w >> 1) * 64, wn = (w & 1) * 64;
    const int bz = blockIdx.z;
    const int n0 = blockIdx.x * 128, m0 = blockIdx.y * 128;

    const bf16* arh = Ahi + bz * sA + (size_t)m0 * K;
    const bf16* arl = Alo + bz * sA + (size_t)m0 * K;
    const bf16* brh = Bhi + bz * sB + (size_t)n0 * K;
    const bf16* brl = Blo + bz * sB + (size_t)n0 * K;

    float acc[4][8][4];
#pragma unroll
    for (int i = 0; i < 4; i++)
#pragma unroll
        for (int j = 0; j < 8; j++)
#pragma unroll
            for (int e = 0; e < 4; e++) acc[i][j][e] = 0.f;

    // cp.async loader mapping: 512 16B segs per matrix, 4 per thread
    const int rbase = t >> 2, seg = t & 3;

    // ldmatrix lane address components
    const uint32_t a_row = (uint32_t)(wm + ((lane >> 3) & 1) * 8 + (lane & 7));
    const uint32_t a_kb = ((lane >> 4) & 1) * 16;
    const uint32_t b_row = (uint32_t)(wn + ((lane >> 4) & 1) * 8 + (lane & 7));
    const uint32_t b_kb = ((lane >> 3) & 1) * 16;

    const int nsteps = K >> 5;

    auto issue = [&](int s) {
        int kc = s << 5;
        uint32_t b0 = sb + (uint32_t)(s % NSTAGE) * STAGEB;
#pragma unroll
        for (int j = 0; j < 4; j++) {
            int r = rbase + 32 * j;
            uint32_t so = SWZ(r, seg * 16);
            size_t go = (size_t)r * K + kc + seg * 8;
            cpa16(b0 + so, arh + go);
            cpa16(b0 + MATB + so, arl + go);
            cpa16(b0 + 2 * MATB + so, brh + go);
            cpa16(b0 + 3 * MATB + so, brl + go);
        }
        CP_COMMIT();
    };

    issue(0);
    issue(1);

    for (int s = 0; s < nsteps; s++) {
        CP_WAIT1();
        __syncthreads();
        if (s + 2 < nsteps) issue(s + 2);

        uint32_t stg = sb + (uint32_t)(s % NSTAGE) * STAGEB;
        uint32_t pAh = stg, pAl = stg + MATB;
        uint32_t pBh = stg + 2 * MATB, pBl = stg + 3 * MATB;
#pragma unroll
        for (int kk = 0; kk < 2; kk++) {
            uint32_t kb = (uint32_t)kk * 32;
            uint32_t Ah[4][4], Al[4][4];
#pragma unroll
            for (int mf = 0; mf < 4; mf++) {
                uint32_t ad = SWZ(a_row + mf * 16, kb + a_kb);
                ldsm_x4(Ah[mf], pAh + ad);
                ldsm_x4(Al[mf], pAl + ad);
            }
#pragma unroll
            for (int p = 0; p < 4; p++) {
                uint32_t bd = SWZ(b_row + p * 16, kb + b_kb);
                uint32_t Bh[4], Bl[4];
                ldsm_x4(Bh, pBh + bd);
                ldsm_x4(Bl, pBl + bd);
#pragma unroll
                for (int mf = 0; mf < 4; mf++) {
                    mma16816(acc[mf][2 * p], Ah[mf], Bh);
                    mma16816(acc[mf][2 * p], Ah[mf], Bl);
                    mma16816(acc[mf][2 * p], Al[mf], Bh);
                    mma16816(acc[mf][2 * p + 1], Ah[mf], Bh + 2);
                    mma16816(acc[mf][2 * p + 1], Ah[mf], Bl + 2);
                    mma16816(acc[mf][2 * p + 1], Al[mf], Bh + 2);
                }
            }
        }
        __syncthreads();
    }

    // ---- epilogue: direct row-major [m][n] store -------------------------
#pragma unroll
    for (int mf = 0; mf < 4; mf++) {
        int mA = m0 + wm + mf * 16 + g;
        int mB = mA + 8;
        float bmA = 0.f, bmB = 0.f;
        if (MODE == 1 || MODE == 4) { bmA = bias[mA]; bmB = bias[mB]; }
#pragma unroll
        for (int nf = 0; nf < 8; nf++) {
            int n = n0 + wn + nf * 8 + tg * 2;
            float v0 = acc[mf][nf][0], v1 = acc[mf][nf][1];
            float v2 = acc[mf][nf][2], v3 = acc[mf][nf][3];
            if (MODE == 0) {
                float bn0 = bias[n], bn1 = bias[n + 1];
                v0 += bn0; v1 += bn1; v2 += bn0; v3 += bn1;
            }
            if (MODE == 1 || MODE == 4) { v0 += bmA; v1 += bmA; v2 += bmB; v3 += bmB; }
            if (MODE == 2) { v0 *= scale; v1 *= scale; v2 *= scale; v3 *= scale; }
            size_t iA = bz * sO + (size_t)mA * ldO + n;
            size_t iB = bz * sO + (size_t)mB * ldO + n;
            if (MODE == 4) {
                v0 += resid[iA]; v1 += resid[iA + 1];
                v2 += resid[iB]; v3 += resid[iB + 1];
            }
            if (MODE == 2 || MODE == 4) {
                *(float2*)&Of[iA] = make_float2(v0, v1);
                *(float2*)&Of[iB] = make_float2(v2, v3);
            } else {
                bf16 h0 = __float2bfloat16(v0), h1 = __float2bfloat16(v1);
                bf16 h2 = __float2bfloat16(v2), h3 = __float2bfloat16(v3);
                __nv_bfloat162 hA; hA.x = h0; hA.y = h1;
                __nv_bfloat162 hB; hB.x = h2; hB.y = h3;
                *(__nv_bfloat162*)&Ohi[iA] = hA;
                *(__nv_bfloat162*)&Ohi[iB] = hB;
                __nv_bfloat162 lA, lB;
                lA.x = __float2bfloat16(v0 - __bfloat162float(h0));
                lA.y = __float2bfloat16(v1 - __bfloat162float(h1));
                lB.x = __float2bfloat16(v2 - __bfloat162float(h2));
                lB.y = __float2bfloat16(v3 - __bfloat162float(h3));
                *(__nv_bfloat162*)&Olo[iA] = lA;
                *(__nv_bfloat162*)&Olo[iB] = lB;
            }
        }
    }
}

// ---------------------------------------------------------------------------
// GroupNorm stats
// ---------------------------------------------------------------------------
__global__ void gn_stats(const float* __restrict__ x) {
    int bg = blockIdx.x;
    int bb = bg / G, g = bg % G;
    const float* xp = x + ((size_t)bb * CC + (size_t)g * CG) * HW;
    const int n = CG * HW;

    float s = 0.f, ss = 0.f;
    for (int i = threadIdx.x; i < n; i += blockDim.x) {
        float v = xp[i];
        s += v;
        ss += v * v;
    }
    __shared__ float sh0[256], sh1[256];
    sh0[threadIdx.x] = s;
    sh1[threadIdx.x] = ss;
    __syncthreads();
    for (int o = 128; o > 0; o >>= 1) {
        if (threadIdx.x < o) {
            sh0[threadIdx.x] += sh0[threadIdx.x + o];
            sh1[threadIdx.x] += sh1[threadIdx.x + o];
        }
        __syncthreads();
    }
    if (threadIdx.x == 0) {
        float mu = sh0[0] / n;
        float var = sh1[0] / n - mu * mu;
        g_stats[bg * 2] = mu;
        g_stats[bg * 2 + 1] = rsqrtf(var + EPS);
    }
}

// GroupNorm apply + transpose: x[b][c][i] -> Ht[b][i][c] bf16 hi/lo
__global__ void gn_transpose(const float* __restrict__ x,
                             const float* __restrict__ gw,
                             const float* __restrict__ gb) {
    __shared__ float tile[32][33];
    int bz = blockIdx.z;
    int i0 = blockIdx.x * 32, c0 = blockIdx.y * 32;
    int tx = threadIdx.x, ty = threadIdx.y;
    const float* xb = x + (size_t)bz * CC * HW;
#pragma unroll
    for (int r = 0; r < 4; r++) {
        int c = c0 + ty + r * 8;
        float mu = g_stats[(bz * G + (c >> 4)) * 2];
        float ri = g_stats[(bz * G + (c >> 4)) * 2 + 1];
        float v = xb[(size_t)c * HW + i0 + tx];
        tile[ty + r * 8][tx] = (v - mu) * ri * gw[c] + gb[c];
    }
    __syncthreads();
    size_t ob = (size_t)bz * HW * CC;
#pragma unroll
    for (int r = 0; r < 4; r++) {
        int i = i0 + ty + r * 8;
        float v = tile[tx][ty + r * 8];
        bf16 h = __float2bfloat16(v);
        size_t idx = ob + (size_t)i * CC + c0 + tx;
        g_ht_hi[idx] = h;
        g_ht_lo[idx] = __float2bfloat16(v - __bfloat162float(h));
    }
}

// fp32 -> bf16 hi/lo split for all 4 weight matrices in one launch
__global__ void wconv4(const float* __restrict__ w0, const float* __restrict__ w1,
                       const float* __restrict__ w2, const float* __restrict__ w3,
                       bf16* __restrict__ hi, bf16* __restrict__ lo) {
    const int NW = CC * CC;
    int i = blockIdx.x * blockDim.x + threadIdx.x;
    int which = blockIdx.y;
    const float* w = which == 0 ? w0 : which == 1 ? w1 : which == 2 ? w2 : w3;
    float v = w[i];
    bf16 h = __float2bfloat16(v);
    hi[which * NW + i] = h;
    lo[which * NW + i] = __float2bfloat16(v - __bfloat162float(h));
}

// Row softmax over 1024 columns; writes P as bf16 hi/lo
__global__ void softmax_kernel(const float* __restrict__ S,
                               bf16* __restrict__ Ph, bf16* __restrict__ Pl) {
    const float* row = S + (size_t)blockIdx.x * HW;
    int t = threadIdx.x;
    float4 v = ((const float4*)row)[t];

    __shared__ float sh[256];
    float m = fmaxf(fmaxf(v.x, v.y), fmaxf(v.z, v.w));
    sh[t] = m;
    __syncthreads();
    for (int o = 128; o > 0; o >>= 1) {
        if (t < o) sh[t] = fmaxf(sh[t], sh[t + o]);
        __syncthreads();
    }
    m = sh[0];
    __syncthreads();

    v.x = __expf(v.x - m); v.y = __expf(v.y - m);
    v.z = __expf(v.z - m); v.w = __expf(v.w - m);
    sh[t] = v.x + v.y + v.z + v.w;
    __syncthreads();
    for (int o = 128; o > 0; o >>= 1) {
        if (t < o) sh[t] += sh[t + o];
        __syncthreads();
    }
    float inv = 1.0f / sh[0];
    float p[4] = {v.x * inv, v.y * inv, v.z * inv, v.w * inv};
    size_t base = (size_t)blockIdx.x * HW + t * 4;
#pragma unroll
    for (int e = 0; e < 4; e++) {
        bf16 h = __float2bfloat16(p[e]);
        Ph[base + e] = h;
        Pl[base + e] = __float2bfloat16(p[e] - __bfloat162float(h));
    }
}

// ---------------------------------------------------------------------------
extern "C" void kernel_launch(void* const* d_in, const int* in_sizes, int n_in,
                              void* d_out, int out_size) {
    const float* x    = (const float*)d_in[0];
    const float* gn_w = (const float*)d_in[2];
    const float* gn_b = (const float*)d_in[3];
    const float* q_w  = (const float*)d_in[4];
    const float* q_b  = (const float*)d_in[5];
    const float* k_w  = (const float*)d_in[6];
    const float* k_b  = (const float*)d_in[7];
    const float* v_w  = (const float*)d_in[8];
    const float* v_b  = (const float*)d_in[9];
    const float* p_w  = (const float*)d_in[10];
    const float* p_b  = (const float*)d_in[11];
    float* out = (float*)d_out;

    bf16 *ht_hi, *ht_lo, *qt_hi, *qt_lo, *kt_hi, *kt_lo, *v_hi, *v_lo;
    bf16 *p_hi, *p_lo, *ot_hi, *ot_lo, *w_hi, *w_lo;
    float* s;
    cudaGetSymbolAddress((void**)&ht_hi, g_ht_hi);
    cudaGetSymbolAddress((void**)&ht_lo, g_ht_lo);
    cudaGetSymbolAddress((void**)&qt_hi, g_qt_hi);
    cudaGetSymbolAddress((void**)&qt_lo, g_qt_lo);
    cudaGetSymbolAddress((void**)&kt_hi, g_kt_hi);
    cudaGetSymbolAddress((void**)&kt_lo, g_kt_lo);
    cudaGetSymbolAddress((void**)&v_hi, g_v_hi);
    cudaGetSymbolAddress((void**)&v_lo, g_v_lo);
    cudaGetSymbolAddress((void**)&p_hi, g_p_hi);
    cudaGetSymbolAddress((void**)&p_lo, g_p_lo);
    cudaGetSymbolAddress((void**)&ot_hi, g_ot_hi);
    cudaGetSymbolAddress((void**)&ot_lo, g_ot_lo);
    cudaGetSymbolAddress((void**)&w_hi, g_w_hi);
    cudaGetSymbolAddress((void**)&w_lo, g_w_lo);
    cudaGetSymbolAddress((void**)&s, g_s);

    cudaFuncSetAttribute(gemm_mma<0>, cudaFuncAttributeMaxDynamicSharedMemorySize, SMEM_TOTAL);
    cudaFuncSetAttribute(gemm_mma<1>, cudaFuncAttributeMaxDynamicSharedMemorySize, SMEM_TOTAL);
    cudaFuncSetAttribute(gemm_mma<2>, cudaFuncAttributeMaxDynamicSharedMemorySize, SMEM_TOTAL);
    cudaFuncSetAttribute(gemm_mma<3>, cudaFuncAttributeMaxDynamicSharedMemorySize, SMEM_TOTAL);
    cudaFuncSetAttribute(gemm_mma<4>, cudaFuncAttributeMaxDynamicSharedMemorySize, SMEM_TOTAL);

    const size_t sHC = (size_t)HW * CC;
    const size_t sSS = (size_t)HW * HW;
    const int NW = CC * CC;
    const float scale = 0.044194173824159216f;  // 512^-0.5

    gn_stats<<<BATCH * G, 256>>>(x);
    gn_transpose<<<dim3(HW / 32, CC / 32, BATCH), dim3(32, 8)>>>(x, gn_w, gn_b);
    wconv4<<<dim3(NW / 256, 4), 256>>>(q_w, k_w, v_w, p_w, w_hi, w_lo);

    // Qt[i][c] = Ht[i]·Wq[c] + qb[c]   (bias on n)
    gemm_mma<0><<<dim3(4, 8, BATCH), 128, SMEM_TOTAL>>>(
        ht_hi, ht_lo, sHC, w_hi + 0 * NW, w_lo + 0 * NW, 0, CC,
        q_b, 0.f, nullptr, qt_hi, qt_lo, nullptr, CC, sHC);
    // Kt[i][c]
    gemm_mma<0><<<dim3(4, 8, BATCH), 128, SMEM_TOTAL>>>(
        ht_hi, ht_lo, sHC, w_hi + 1 * NW, w_lo + 1 * NW, 0, CC,
        k_b, 0.f, nullptr, kt_hi, kt_lo, nullptr, CC, sHC);
    // V[c][j] = Wv[c]·Ht[j] + vb[c]    (bias on m)
    gemm_mma<1><<<dim3(8, 4, BATCH), 128, SMEM_TOTAL>>>(
        w_hi + 2 * NW, w_lo + 2 * NW, 0, ht_hi, ht_lo, sHC, CC,
        v_b, 0.f, nullptr, v_hi, v_lo, nullptr, HW, sHC);
    // S[i][j] = scale * Qt[i]·Kt[j]
    gemm_mma<2><<<dim3(8, 8, BATCH), 128, SMEM_TOTAL>>>(
        qt_hi, qt_lo, sHC, kt_hi, kt_lo, sHC, CC,
        nullptr, scale, nullptr, nullptr, nullptr, s, HW, sSS);

    softmax_kernel<<<BATCH * HW, 256>>>(s, p_hi, p_lo);

    // Ot[i][c] = P[i]·V[c]   (K = 1024)
    gemm_mma<3><<<dim3(4, 8, BATCH), 128, SMEM_TOTAL>>>(
        p_hi, p_lo, sSS, v_hi, v_lo, sHC, HW,
        nullptr, 0.f, nullptr, ot_hi, ot_lo, nullptr, CC, sHC);
    // out[d][i] = x[d][i] + Wp[d]·Ot[i] + pb[d]
    gemm_mma<4><<<dim3(8, 4, BATCH), 128, SMEM_TOTAL>>>(
        w_hi + 3 * NW, w_lo + 3 * NW, 0, ot_hi, ot_lo, sHC, CC,
        p_b, 0.f, x, nullptr, nullptr, out, HW, sHC);
}

// round 9
// speedup vs baseline: 1.1573x; 1.1473x over previous
#include <cuda_runtime.h>
#include <cuda_fp16.h>
#include <cstdint>

#define BATCH 16
#define CC 512
#define HW 1024
#define G 32
#define CG 16
#define EPS 1e-5f

typedef __half fp16;

// ---------------------------------------------------------------------------
// Scratch (device globals)
// ---------------------------------------------------------------------------
__device__ float g_stats[BATCH * G * 2];
__device__ __align__(16) fp16 g_ht_hi[BATCH * HW * CC], g_ht_lo[BATCH * HW * CC];
__device__ __align__(16) fp16 g_t_hi[BATCH * HW * CC],  g_t_lo[BATCH * HW * CC];
__device__ __align__(16) fp16 g_ve_hi[BATCH * CC * HW], g_ve_lo[BATCH * CC * HW];
__device__ __align__(16) float g_s[(size_t)BATCH * HW * HW];
__device__ __align__(16) fp16 g_p_hi[(size_t)BATCH * HW * HW];
__device__ __align__(16) fp16 g_p_lo[(size_t)BATCH * HW * HW];
__device__ __align__(16) fp16 g_wqT_hi[CC * CC], g_wqT_lo[CC * CC];
__device__ __align__(16) fp16 g_wkT_hi[CC * CC], g_wkT_lo[CC * CC];
__device__ __align__(16) fp16 g_wvT_hi[CC * CC], g_wvT_lo[CC * CC];
__device__ __align__(16) fp16 g_wp_hi[CC * CC],  g_wp_lo[CC * CC];
__device__ __align__(16) fp16 g_m2_hi[CC * CC],  g_m2_lo[CC * CC];
__device__ __align__(16) fp16 g_wpv_hi[CC * CC], g_wpv_lo[CC * CC];
__device__ float g_u[CC], g_vbp[CC];

// ---------------------------------------------------------------------------
// PTX helpers
// ---------------------------------------------------------------------------
__device__ __forceinline__ uint32_t smem_u32(const void* p) {
    uint32_t a;
    asm("{ .reg .u64 t; cvta.to.shared.u64 t, %1; cvt.u32.u64 %0, t; }"
        : "=r"(a) : "l"(p));
    return a;
}
__device__ __forceinline__ void cpa16(uint32_t dst, const void* src) {
    asm volatile("cp.async.ca.shared.global [%0], [%1], 16;"
                 :: "r"(dst), "l"(src));
}
#define CP_COMMIT() asm volatile("cp.async.commit_group;" ::: "memory")
#define CP_WAIT1() asm volatile("cp.async.wait_group 1;" ::: "memory")

__device__ __forceinline__ void ldsm_x4(uint32_t* r, uint32_t addr) {
    asm volatile(
        "ldmatrix.sync.aligned.m8n8.x4.shared.b16 {%0,%1,%2,%3}, [%4];"
        : "=r"(r[0]), "=r"(r[1]), "=r"(r[2]), "=r"(r[3]) : "r"(addr));
}
__device__ __forceinline__ void mma16816(float* c, const uint32_t* a,
                                         const uint32_t* b) {
    asm volatile(
        "mma.sync.aligned.m16n8k16.row.col.f32.f16.f16.f32 "
        "{%0,%1,%2,%3}, {%4,%5,%6,%7}, {%8,%9}, {%0,%1,%2,%3};"
        : "+f"(c[0]), "+f"(c[1]), "+f"(c[2]), "+f"(c[3])
        : "r"(a[0]), "r"(a[1]), "r"(a[2]), "r"(a[3]), "r"(b[0]), "r"(b[1]));
}

// Swizzled 64B-row layout: conflict-free for ldmatrix + cp.async
#define SWZ(row, kb) \
    ((uint32_t)(row) * 64u + (((((uint32_t)(kb)) >> 4) ^ (((uint32_t)(row) >> 1) & 3u)) << 4))

#define MATB 8192u           // 128 rows * 64 B
#define STAGEB 32768u        // 4 matrices (Ah, Al, Bh, Bl)
#define NSTAGE 3
#define SMEM_TOTAL (NSTAGE * STAGEB)

// ---------------------------------------------------------------------------
// 3-term split-fp16 MMA GEMM: D ~= Ah·Bh + Ah·Bl + Al·Bh (fp32 accum)
// D[m][n] = sum_k A[m][k]*B[n][k]; 128x128 tile, BK=32, 4 warps (64x64 tiles).
// MODE 0: +bias[n], fp16 hi/lo out
// MODE 1: +bias[m], fp16 hi/lo out
// MODE 2: *scale,   f32 out
// MODE 3: plain,    fp16 hi/lo out
// MODE 4: +bias[m]+resid, f32 out
// ---------------------------------------------------------------------------
template <int MODE>
__global__ void __launch_bounds__(128, 2)
gemm_mma(const fp16* __restrict__ Ahi, const fp16* __restrict__ Alo, size_t sA,
         const fp16* __restrict__ Bhi, const fp16* __restrict__ Blo, size_t sB,
         int K, const float* __restrict__ bias, float scale,
         const float* __restrict__ resid,
         fp16* __restrict__ Ohi, fp16* __restrict__ Olo, float* __restrict__ Of,
         int ldO, size_t sO) {
    extern __shared__ char smem[];
    const uint32_t sb = smem_u32(smem);

    const int t = threadIdx.x;
    const int w = t >> 5, lane = t & 31;
    const int g = lane >> 2, tg = lane & 3;
    const int wm = (w >> 1) * 64, wn = (w & 1) * 64;
    const int bz = blockIdx.z;
    const int n0 = blockIdx.x * 128, m0 = blockIdx.y * 128;

    const fp16* arh = Ahi + bz * sA + (size_t)m0 * K;
    const fp16* arl = Alo + bz * sA + (size_t)m0 * K;
    const fp16* brh = Bhi + bz * sB + (size_t)n0 * K;
    const fp16* brl = Blo + bz * sB + (size_t)n0 * K;

    float acc[4][8][4];
#pragma unroll
    for (int i = 0; i < 4; i++)
#pragma unroll
        for (int j = 0; j < 8; j++)
#pragma unroll
            for (int e = 0; e < 4; e++) acc[i][j][e] = 0.f;

    const int rbase = t >> 2, seg = t & 3;

    const uint32_t a_row = (uint32_t)(wm + ((lane >> 3) & 1) * 8 + (lane & 7));
    const uint32_t a_kb = ((lane >> 4) & 1) * 16;
    const uint32_t b_row = (uint32_t)(wn + ((lane >> 4) & 1) * 8 + (lane & 7));
    const uint32_t b_kb = ((lane >> 3) & 1) * 16;

    const int nsteps = K >> 5;

    auto issue = [&](int s) {
        int kc = s << 5;
        uint32_t b0 = sb + (uint32_t)(s % NSTAGE) * STAGEB;
#pragma unroll
        for (int j = 0; j < 4; j++) {
            int r = rbase + 32 * j;
            uint32_t so = SWZ(r, seg * 16);
            size_t go = (size_t)r * K + kc + seg * 8;
            cpa16(b0 + so, arh + go);
            cpa16(b0 + MATB + so, arl + go);
            cpa16(b0 + 2 * MATB + so, brh + go);
            cpa16(b0 + 3 * MATB + so, brl + go);
        }
        CP_COMMIT();
    };

    issue(0);
    issue(1);

    for (int s = 0; s < nsteps; s++) {
        CP_WAIT1();
        __syncthreads();
        if (s + 2 < nsteps) issue(s + 2);

        uint32_t stg = sb + (uint32_t)(s % NSTAGE) * STAGEB;
        uint32_t pAh = stg, pAl = stg + MATB;
        uint32_t pBh = stg + 2 * MATB, pBl = stg + 3 * MATB;
#pragma unroll
        for (int kk = 0; kk < 2; kk++) {
            uint32_t kb = (uint32_t)kk * 32;
            uint32_t Ah[4][4], Al[4][4];
#pragma unroll
            for (int mf = 0; mf < 4; mf++) {
                uint32_t ad = SWZ(a_row + mf * 16, kb + a_kb);
                ldsm_x4(Ah[mf], pAh + ad);
                ldsm_x4(Al[mf], pAl + ad);
            }
#pragma unroll
            for (int p = 0; p < 4; p++) {
                uint32_t bd = SWZ(b_row + p * 16, kb + b_kb);
                uint32_t Bh[4], Bl[4];
                ldsm_x4(Bh, pBh + bd);
                ldsm_x4(Bl, pBl + bd);
#pragma unroll
                for (int mf = 0; mf < 4; mf++) {
                    mma16816(acc[mf][2 * p], Ah[mf], Bh);
                    mma16816(acc[mf][2 * p], Ah[mf], Bl);
                    mma16816(acc[mf][2 * p], Al[mf], Bh);
                    mma16816(acc[mf][2 * p + 1], Ah[mf], Bh + 2);
                    mma16816(acc[mf][2 * p + 1], Ah[mf], Bl + 2);
                    mma16816(acc[mf][2 * p + 1], Al[mf], Bh + 2);
                }
            }
        }
        __syncthreads();
    }

    // ---- epilogue: direct row-major [m][n] store -------------------------
#pragma unroll
    for (int mf = 0; mf < 4; mf++) {
        int mA = m0 + wm + mf * 16 + g;
        int mB = mA + 8;
        float bmA = 0.f, bmB = 0.f;
        if (MODE == 1 || MODE == 4) { bmA = bias[mA]; bmB = bias[mB]; }
#pragma unroll
        for (int nf = 0; nf < 8; nf++) {
            int n = n0 + wn + nf * 8 + tg * 2;
            float v0 = acc[mf][nf][0], v1 = acc[mf][nf][1];
            float v2 = acc[mf][nf][2], v3 = acc[mf][nf][3];
            if (MODE == 0) {
                float bn0 = bias[n], bn1 = bias[n + 1];
                v0 += bn0; v1 += bn1; v2 += bn0; v3 += bn1;
            }
            if (MODE == 1 || MODE == 4) { v0 += bmA; v1 += bmA; v2 += bmB; v3 += bmB; }
            if (MODE == 2) { v0 *= scale; v1 *= scale; v2 *= scale; v3 *= scale; }
            size_t iA = bz * sO + (size_t)mA * ldO + n;
            size_t iB = bz * sO + (size_t)mB * ldO + n;
            if (MODE == 4) {
                v0 += resid[iA]; v1 += resid[iA + 1];
                v2 += resid[iB]; v3 += resid[iB + 1];
            }
            if (MODE == 2 || MODE == 4) {
                *(float2*)&Of[iA] = make_float2(v0, v1);
                *(float2*)&Of[iB] = make_float2(v2, v3);
            } else {
                fp16 h0 = __float2half(v0), h1 = __float2half(v1);
                fp16 h2 = __float2half(v2), h3 = __float2half(v3);
                __half2 hA; hA.x = h0; hA.y = h1;
                __half2 hB; hB.x = h2; hB.y = h3;
                *(__half2*)&Ohi[iA] = hA;
                *(__half2*)&Ohi[iB] = hB;
                __half2 lA, lB;
                lA.x = __float2half(v0 - __half2float(h0));
                lA.y = __float2half(v1 - __half2float(h1));
                lB.x = __float2half(v2 - __half2float(h2));
                lB.y = __float2half(v3 - __half2float(h3));
                *(__half2*)&Olo[iA] = lA;
                *(__half2*)&Olo[iB] = lB;
            }
        }
    }
}

// ---------------------------------------------------------------------------
// GroupNorm stats
// ---------------------------------------------------------------------------
__global__ void gn_stats(const float* __restrict__ x) {
    int bg = blockIdx.x;
    int bb = bg / G, g = bg % G;
    const float* xp = x + ((size_t)bb * CC + (size_t)g * CG) * HW;
    const int n = CG * HW;

    float s = 0.f, ss = 0.f;
    for (int i = threadIdx.x; i < n; i += blockDim.x) {
        float v = xp[i];
        s += v;
        ss += v * v;
    }
    __shared__ float sh0[256], sh1[256];
    sh0[threadIdx.x] = s;
    sh1[threadIdx.x] = ss;
    __syncthreads();
    for (int o = 128; o > 0; o >>= 1) {
        if (threadIdx.x < o) {
            sh0[threadIdx.x] += sh0[threadIdx.x + o];
            sh1[threadIdx.x] += sh1[threadIdx.x + o];
        }
        __syncthreads();
    }
    if (threadIdx.x == 0) {
        float mu = sh0[0] / n;
        float var = sh1[0] / n - mu * mu;
        g_stats[bg * 2] = mu;
        g_stats[bg * 2 + 1] = rsqrtf(var + EPS);
    }
}

// GroupNorm apply + transpose: x[b][c][i] -> Ht[b][i][c] fp16 hi/lo
__global__ void gn_transpose(const float* __restrict__ x,
                             const float* __restrict__ gw,
                             const float* __restrict__ gb) {
    __shared__ float tile[32][33];
    int bz = blockIdx.z;
    int i0 = blockIdx.x * 32, c0 = blockIdx.y * 32;
    int tx = threadIdx.x, ty = threadIdx.y;
    const float* xb = x + (size_t)bz * CC * HW;
#pragma unroll
    for (int r = 0; r < 4; r++) {
        int c = c0 + ty + r * 8;
        float mu = g_stats[(bz * G + (c >> 4)) * 2];
        float ri = g_stats[(bz * G + (c >> 4)) * 2 + 1];
        float v = xb[(size_t)c * HW + i0 + tx];
        tile[ty + r * 8][tx] = (v - mu) * ri * gw[c] + gb[c];
    }
    __syncthreads();
    size_t ob = (size_t)bz * HW * CC;
#pragma unroll
    for (int r = 0; r < 4; r++) {
        int i = i0 + ty + r * 8;
        float v = tile[tx][ty + r * 8];
        fp16 h = __float2half(v);
        size_t idx = ob + (size_t)i * CC + c0 + tx;
        g_ht_hi[idx] = h;
        g_ht_lo[idx] = __float2half(v - __half2float(h));
    }
}

// Transpose+split 3 weight matrices: out[z][a][d] = w_z[d][a] as fp16 hi/lo
__global__ void wtransT(const float* __restrict__ w0, const float* __restrict__ w1,
                        const float* __restrict__ w2) {
    __shared__ float tile[32][33];
    int z = blockIdx.z;
    const float* w = z == 0 ? w0 : z == 1 ? w1 : w2;
    fp16* ohi = z == 0 ? g_wqT_hi : z == 1 ? g_wkT_hi : g_wvT_hi;
    fp16* olo = z == 0 ? g_wqT_lo : z == 1 ? g_wkT_lo : g_wvT_lo;
    int d0 = blockIdx.x * 32, a0 = blockIdx.y * 32;
    int tx = threadIdx.x, ty = threadIdx.y;
#pragma unroll
    for (int r = 0; r < 4; r++)
        tile[ty + r * 8][tx] = w[(size_t)(d0 + ty + r * 8) * CC + a0 + tx];
    __syncthreads();
#pragma unroll
    for (int r = 0; r < 4; r++) {
        int a = a0 + ty + r * 8;
        float v = tile[tx][ty + r * 8];  // = w[d0+tx][a]
        fp16 h = __float2half(v);
        size_t idx = (size_t)a * CC + d0 + tx;
        ohi[idx] = h;
        olo[idx] = __float2half(v - __half2float(h));
    }
}

// Straight split of Wp
__global__ void wsplit(const float* __restrict__ w) {
    int i = blockIdx.x * blockDim.x + threadIdx.x;
    float v = w[i];
    fp16 h = __float2half(v);
    g_wp_hi[i] = h;
    g_wp_lo[i] = __float2half(v - __half2float(h));
}

// u[b] = sum_d qb[d]*Wk[d][b]
__global__ void ubias(const float* __restrict__ qb, const float* __restrict__ wk) {
    int b = blockIdx.x * blockDim.x + threadIdx.x;
    float s = 0.f;
    for (int d = 0; d < CC; d++) s += qb[d] * wk[(size_t)d * CC + b];
    g_u[b] = s;
}

// vbp[d] = sum_c Wp[d][c]*vb[c]   (one block per d)
__global__ void vbias(const float* __restrict__ wp, const float* __restrict__ vb) {
    int d = blockIdx.x;
    float s = 0.f;
    for (int c = threadIdx.x; c < CC; c += blockDim.x)
        s += wp[(size_t)d * CC + c] * vb[c];
    __shared__ float sh[256];
    sh[threadIdx.x] = s;
    __syncthreads();
    for (int o = 128; o > 0; o >>= 1) {
        if (threadIdx.x < o) sh[threadIdx.x] += sh[threadIdx.x + o];
        __syncthreads();
    }
    if (threadIdx.x == 0) g_vbp[d] = sh[0];
}

// Row softmax over 1024 columns; writes P as fp16 hi/lo
__global__ void softmax_kernel(const float* __restrict__ S,
                               fp16* __restrict__ Ph, fp16* __restrict__ Pl) {
    const float* row = S + (size_t)blockIdx.x * HW;
    int t = threadIdx.x;
    float4 v = ((const float4*)row)[t];

    __shared__ float sh[256];
    float m = fmaxf(fmaxf(v.x, v.y), fmaxf(v.z, v.w));
    sh[t] = m;
    __syncthreads();
    for (int o = 128; o > 0; o >>= 1) {
        if (t < o) sh[t] = fmaxf(sh[t], sh[t + o]);
        __syncthreads();
    }
    m = sh[0];
    __syncthreads();

    v.x = __expf(v.x - m); v.y = __expf(v.y - m);
    v.z = __expf(v.z - m); v.w = __expf(v.w - m);
    sh[t] = v.x + v.y + v.z + v.w;
    __syncthreads();
    for (int o = 128; o > 0; o >>= 1) {
        if (t < o) sh[t] += sh[t + o];
        __syncthreads();
    }
    float inv = 1.0f / sh[0];
    float p[4] = {v.x * inv, v.y * inv, v.z * inv, v.w * inv};
    size_t base = (size_t)blockIdx.x * HW + t * 4;
#pragma unroll
    for (int e = 0; e < 4; e++) {
        fp16 h = __float2half(p[e]);
        Ph[base + e] = h;
        Pl[base + e] = __float2half(p[e] - __half2float(h));
    }
}

// ---------------------------------------------------------------------------
extern "C" void kernel_launch(void* const* d_in, const int* in_sizes, int n_in,
                              void* d_out, int out_size) {
    const float* x    = (const float*)d_in[0];
    const float* gn_w = (const float*)d_in[2];
    const float* gn_b = (const float*)d_in[3];
    const float* q_w  = (const float*)d_in[4];
    const float* q_b  = (const float*)d_in[5];
    const float* k_w  = (const float*)d_in[6];
    const float* v_w  = (const float*)d_in[8];
    const float* v_b  = (const float*)d_in[9];
    const float* p_w  = (const float*)d_in[10];
    const float* p_b  = (const float*)d_in[11];
    float* out = (float*)d_out;

    fp16 *ht_hi, *ht_lo, *t_hi, *t_lo, *ve_hi, *ve_lo, *p_hi, *p_lo;
    fp16 *wqT_hi, *wqT_lo, *wkT_hi, *wkT_lo, *wvT_hi, *wvT_lo;
    fp16 *wp_hi, *wp_lo, *m2_hi, *m2_lo, *wpv_hi, *wpv_lo;
    float *s, *u, *vbp;
    cudaGetSymbolAddress((void**)&ht_hi, g_ht_hi);
    cudaGetSymbolAddress((void**)&ht_lo, g_ht_lo);
    cudaGetSymbolAddress((void**)&t_hi, g_t_hi);
    cudaGetSymbolAddress((void**)&t_lo, g_t_lo);
    cudaGetSymbolAddress((void**)&ve_hi, g_ve_hi);
    cudaGetSymbolAddress((void**)&ve_lo, g_ve_lo);
    cudaGetSymbolAddress((void**)&p_hi, g_p_hi);
    cudaGetSymbolAddress((void**)&p_lo, g_p_lo);
    cudaGetSymbolAddress((void**)&wqT_hi, g_wqT_hi);
    cudaGetSymbolAddress((void**)&wqT_lo, g_wqT_lo);
    cudaGetSymbolAddress((void**)&wkT_hi, g_wkT_hi);
    cudaGetSymbolAddress((void**)&wkT_lo, g_wkT_lo);
    cudaGetSymbolAddress((void**)&wvT_hi, g_wvT_hi);
    cudaGetSymbolAddress((void**)&wvT_lo, g_wvT_lo);
    cudaGetSymbolAddress((void**)&wp_hi, g_wp_hi);
    cudaGetSymbolAddress((void**)&wp_lo, g_wp_lo);
    cudaGetSymbolAddress((void**)&m2_hi, g_m2_hi);
    cudaGetSymbolAddress((void**)&m2_lo, g_m2_lo);
    cudaGetSymbolAddress((void**)&wpv_hi, g_wpv_hi);
    cudaGetSymbolAddress((void**)&wpv_lo, g_wpv_lo);
    cudaGetSymbolAddress((void**)&s, g_s);
    cudaGetSymbolAddress((void**)&u, g_u);
    cudaGetSymbolAddress((void**)&vbp, g_vbp);

    cudaFuncSetAttribute(gemm_mma<0>, cudaFuncAttributeMaxDynamicSharedMemorySize, SMEM_TOTAL);
    cudaFuncSetAttribute(gemm_mma<1>, cudaFuncAttributeMaxDynamicSharedMemorySize, SMEM_TOTAL);
    cudaFuncSetAttribute(gemm_mma<2>, cudaFuncAttributeMaxDynamicSharedMemorySize, SMEM_TOTAL);
    cudaFuncSetAttribute(gemm_mma<3>, cudaFuncAttributeMaxDynamicSharedMemorySize, SMEM_TOTAL);
    cudaFuncSetAttribute(gemm_mma<4>, cudaFuncAttributeMaxDynamicSharedMemorySize, SMEM_TOTAL);

    const size_t sHC = (size_t)HW * CC;
    const size_t sSS = (size_t)HW * HW;
    const float scale = 0.044194173824159216f;  // 512^-0.5

    // GroupNorm + transposed split
    gn_stats<<<BATCH * G, 256>>>(x);
    gn_transpose<<<dim3(HW / 32, CC / 32, BATCH), dim3(32, 8)>>>(x, gn_w, gn_b);

    // Weight preprocessing (all tiny)
    wtransT<<<dim3(16, 16, 3), dim3(32, 8)>>>(q_w, k_w, v_w);
    wsplit<<<CC * CC / 256, 256>>>(p_w);
    ubias<<<CC / 128, 128>>>(q_b, k_w);
    vbias<<<CC, 256>>>(p_w, v_b);

    // M2[b][a] = sum_d Wk[d][b]*Wq[d][a]   (so S = Ht·M·Ht^T works K-major)
    gemm_mma<3><<<dim3(4, 4, 1), 128, SMEM_TOTAL>>>(
        wkT_hi, wkT_lo, 0, wqT_hi, wqT_lo, 0, CC,
        nullptr, 0.f, nullptr, m2_hi, m2_lo, nullptr, CC, 0);
    // Wpv[d][c'] = sum_c Wp[d][c]*Wv[c][c']
    gemm_mma<3><<<dim3(4, 4, 1), 128, SMEM_TOTAL>>>(
        wp_hi, wp_lo, 0, wvT_hi, wvT_lo, 0, CC,
        nullptr, 0.f, nullptr, wpv_hi, wpv_lo, nullptr, CC, 0);

    // T[i][b] = sum_a Ht[i][a]*M2[b][a] + u[b]
    gemm_mma<0><<<dim3(4, 8, BATCH), 128, SMEM_TOTAL>>>(
        ht_hi, ht_lo, sHC, m2_hi, m2_lo, 0, CC,
        u, 0.f, nullptr, t_hi, t_lo, nullptr, CC, sHC);
    // S[i][j] = scale * sum_b T[i][b]*Ht[j][b]
    gemm_mma<2><<<dim3(8, 8, BATCH), 128, SMEM_TOTAL>>>(
        t_hi, t_lo, sHC, ht_hi, ht_lo, sHC, CC,
        nullptr, scale, nullptr, nullptr, nullptr, s, HW, sSS);

    softmax_kernel<<<BATCH * HW, 256>>>(s, p_hi, p_lo);

    // Ve[d][j] = sum_c Wpv[d][c]*Ht[j][c] + (Wp·vb)[d]
    gemm_mma<1><<<dim3(8, 4, BATCH), 128, SMEM_TOTAL>>>(
        wpv_hi, wpv_lo, 0, ht_hi, ht_lo, sHC, CC,
        vbp, 0.f, nullptr, ve_hi, ve_lo, nullptr, HW, sHC);
    // out[d][i] = x[d][i] + sum_j Ve[d][j]*P[i][j] + p_b[d]
    gemm_mma<4><<<dim3(8, 4, BATCH), 128, SMEM_TOTAL>>>(
        ve_hi, ve_lo, sHC, p_hi, p_lo, sSS, HW,
        p_b, 0.f, x, nullptr, nullptr, out, HW, sHC);
}